// round 7
// baseline (speedup 1.0000x reference)
#include <cuda_runtime.h>
#include <cuda_bf16.h>
#include <cstdint>

#define BATCH  8
#define CIN    128
#define OUTC   128
#define T_IN   32768
#define P_OUT  32769
#define NTILES 2056          // 257 p-tiles * 8 batches
#define GRIDX  152

#define WP 132               // u64 pitch, W rows (conflict-free LDS.64)
#define AP 132               // u64 pitch, A rows (conflict-free LDS.64)

// smem byte offsets
#define SM_W    0                        // u64 [128][WP]  = 135168
#define SM_A0   135168                   // u64 [32][AP]   = 33792
#define SM_A1   168960
#define SM_BIAS 202752
#define SM_TOT  203264

typedef unsigned long long u64;

// W image: [channel r][o] u64 = { lo32: bf16x2 hi-pair, hi32: bf16x2 residual pair }
__device__ __align__(16) u64 g_W64[128 * WP];

__device__ __forceinline__ uint32_t cvt2(float hi, float lo) {
    uint32_t r;
    asm("cvt.rn.bf16x2.f32 %0, %1, %2;" : "=r"(r) : "f"(hi), "f"(lo));
    return r;
}
__device__ __forceinline__ uint32_t lo_resid(uint32_t h, float xhi, float xlo) {
    float fh = __uint_as_float(h & 0xffff0000u);
    float fl = __uint_as_float(h << 16);
    return cvt2(xhi - fh, xlo - fl);
}
__device__ __forceinline__ void mma16816(float* d, const uint32_t* a, uint32_t b0, uint32_t b1) {
    asm volatile(
        "mma.sync.aligned.m16n8k16.row.col.f32.bf16.bf16.f32 "
        "{%0,%1,%2,%3}, {%4,%5,%6,%7}, {%8,%9}, {%0,%1,%2,%3};"
        : "+f"(d[0]), "+f"(d[1]), "+f"(d[2]), "+f"(d[3])
        : "r"(a[0]), "r"(a[1]), "r"(a[2]), "r"(a[3]), "r"(b0), "r"(b1));
}
__device__ __forceinline__ void bar_sync(int id)   { asm volatile("bar.sync %0, 512;"   :: "r"(id) : "memory"); }
__device__ __forceinline__ void bar_arrive(int id) { asm volatile("bar.arrive %0, 512;" :: "r"(id) : "memory"); }

__global__ void prep_W(const float* __restrict__ W) {
    int idx = blockIdx.x * blockDim.x + threadIdx.x;   // 16384
    int r = idx >> 7, o = idx & 127;
    float w0 = W[o * 256 + 2 * r];
    float w1 = W[o * 256 + 2 * r + 1];
    uint32_t h = cvt2(w1, w0);
    uint32_t l = lo_resid(h, w1, w0);
    g_W64[r * WP + o] = ((u64)l << 32) | h;
}

// producer LDG: thread (row, q) loads window [p0+16q, p0+16q+18) of channel c*32+row
__device__ __forceinline__ void ldgP(const float* __restrict__ x,
                                     int tile, int c, int row, int q, float* v) {
    int b = tile & 7;
    long p0 = (long)(tile >> 3) * 128;
    const float* gxr = x + (size_t)b * CIN * T_IN + (size_t)(c * 32 + row) * T_IN;
    long pb = p0 + 16 * q;
    if (p0 + 130 <= T_IN) {
        float4 q0 = *reinterpret_cast<const float4*>(gxr + pb);
        float4 q1 = *reinterpret_cast<const float4*>(gxr + pb + 4);
        float4 q2 = *reinterpret_cast<const float4*>(gxr + pb + 8);
        float4 q3 = *reinterpret_cast<const float4*>(gxr + pb + 12);
        v[0]=q0.x; v[1]=q0.y; v[2]=q0.z; v[3]=q0.w;
        v[4]=q1.x; v[5]=q1.y; v[6]=q1.z; v[7]=q1.w;
        v[8]=q2.x; v[9]=q2.y; v[10]=q2.z; v[11]=q2.w;
        v[12]=q3.x; v[13]=q3.y; v[14]=q3.z; v[15]=q3.w;
        v[16]=gxr[pb + 16]; v[17]=gxr[pb + 17];
    } else {
        #pragma unroll
        for (int k = 0; k < 18; ++k) {
            long p = pb + k;
            v[k] = (p < T_IN) ? gxr[p] : 0.0f;
        }
    }
}
// producer STS: q-rotated chunk order -> quarter-warp phases hit 8 distinct bank groups
__device__ __forceinline__ void stsP(u64* __restrict__ buf, int row, int q, const float* v) {
    #pragma unroll
    for (int j = 0; j < 8; ++j) {
        int jj = (j + q) & 7;
        uint32_t h0 = cvt2(v[2*jj + 2], v[2*jj]);
        uint32_t l0 = lo_resid(h0, v[2*jj + 2], v[2*jj]);
        uint32_t h1 = cvt2(v[2*jj + 3], v[2*jj + 1]);
        uint32_t l1 = lo_resid(h1, v[2*jj + 3], v[2*jj + 1]);
        uint4 val; val.x = h0; val.y = l0; val.z = h1; val.w = l1;
        *reinterpret_cast<uint4*>(buf + (size_t)row * AP + 16 * q + 2 * jj) = val;
    }
}

__global__ __launch_bounds__(512, 1)
void dconv7(const float* __restrict__ x,
            const float* __restrict__ bias,
            float* __restrict__ out)
{
    extern __shared__ char smem[];
    u64*   sW    = reinterpret_cast<u64*>(smem + SM_W);
    u64*   sA[2] = { reinterpret_cast<u64*>(smem + SM_A0),
                     reinterpret_cast<u64*>(smem + SM_A1) };
    float* sBias = reinterpret_cast<float*>(smem + SM_BIAS);

    const int tid = threadIdx.x;
    const int warp = tid >> 5;
    const int bx = blockIdx.x;
    const int nt = (NTILES - 1 - bx) / GRIDX + 1;
    const int nchunks = nt * 4;

    // one-time: W image + bias
    {
        const uint4* src = reinterpret_cast<const uint4*>(g_W64);
        uint4* dst = reinterpret_cast<uint4*>(sW);
        #pragma unroll 4
        for (int i = tid; i < 8448; i += 512) dst[i] = src[i];
    }
    if (tid < 128) sBias[tid] = bias[tid];
    __syncthreads();

    if (warp >= 8) {
        // ================= PRODUCER (warps 8-15) =================
        const int tp  = tid & 255;
        const int row = tp >> 3;
        const int q   = tp & 7;
        float v[18];
        ldgP(x, bx, 0, row, q, v);
        for (int i = 0; i < nchunks; ++i) {
            const int s = i & 1;
            if (i >= 2) bar_sync(3 + s);           // wait EMPTY(s)
            float vn[18];
            #pragma unroll
            for (int k = 0; k < 18; ++k) vn[k] = 0.0f;
            if (i + 1 < nchunks) {
                int ii = i + 1;
                ldgP(x, bx + (ii >> 2) * GRIDX, ii & 3, row, q, vn);
            }
            stsP(sA[s], row, q, v);
            bar_arrive(1 + s);                     // signal FULL(s)
            #pragma unroll
            for (int k = 0; k < 18; ++k) v[k] = vn[k];
        }
    } else {
        // ================= CONSUMER (warps 0-7) =================
        const int lane = tid & 31;
        const int t = lane & 3;
        const int g = lane >> 2;
        const int mb = (warp >> 2) * 64;     // M base
        const int nb = (warp & 3) * 32;      // N base

        float acc[4][4][4];
        #pragma unroll
        for (int mf = 0; mf < 4; ++mf)
            #pragma unroll
            for (int nf = 0; nf < 4; ++nf)
                #pragma unroll
                for (int i = 0; i < 4; ++i) acc[mf][nf][i] = 0.0f;

        int i = 0;
        for (int tt = 0; tt < nt; ++tt) {
            #pragma unroll 1
            for (int c = 0; c < 4; ++c, ++i) {
                const int s = i & 1;
                bar_sync(1 + s);                   // wait FULL(s)
                const u64* Ab = sA[s];
                #pragma unroll
                for (int kl = 0; kl < 4; ++kl) {
                    const int lrt = 8 * kl + t;
                    const u64* wr = sW + (size_t)(32 * c + lrt) * WP;
                    u64 w0[4], w1[4];
                    #pragma unroll
                    for (int nf = 0; nf < 4; ++nf) {
                        int o = nb + nf * 8 + g;
                        w0[nf] = wr[o];
                        w1[nf] = wr[4 * WP + o];
                    }
                    const u64* ar = Ab + (size_t)lrt * AP;
                    #pragma unroll
                    for (int mf = 0; mf < 4; ++mf) {
                        const int pos = mb + mf * 16 + g;
                        u64 a0 = ar[pos],          a1 = ar[pos + 8];
                        u64 a2 = ar[4 * AP + pos], a3 = ar[4 * AP + pos + 8];
                        uint32_t ah[4] = { (uint32_t)a0, (uint32_t)a1, (uint32_t)a2, (uint32_t)a3 };
                        uint32_t al[4] = { (uint32_t)(a0 >> 32), (uint32_t)(a1 >> 32),
                                           (uint32_t)(a2 >> 32), (uint32_t)(a3 >> 32) };
                        #pragma unroll
                        for (int nf = 0; nf < 4; ++nf) {
                            uint32_t bh0 = (uint32_t)w0[nf], bl0 = (uint32_t)(w0[nf] >> 32);
                            uint32_t bh1 = (uint32_t)w1[nf], bl1 = (uint32_t)(w1[nf] >> 32);
                            mma16816(acc[mf][nf], ah, bh0, bh1);   // Ahi*Bhi
                            mma16816(acc[mf][nf], al, bh0, bh1);   // Alo*Bhi
                            mma16816(acc[mf][nf], ah, bl0, bl1);   // Ahi*Blo
                        }
                    }
                }
                bar_arrive(3 + s);                 // signal EMPTY(s)
            }

            // epilogue (producers already staging next tile)
            const int tile = bx + tt * GRIDX;
            const int b = tile & 7;
            const long p0 = (long)(tile >> 3) * 128;
            #pragma unroll
            for (int mf = 0; mf < 4; ++mf) {
                long pg = p0 + mb + mf * 16 + g;
                #pragma unroll
                for (int nf = 0; nf < 4; ++nf) {
                    int o = nb + nf * 8 + 2 * t;
                    float b0 = sBias[o], b1 = sBias[o + 1];
                    float* ob = out + ((size_t)b * OUTC + o) * P_OUT + pg;
                    if (pg < P_OUT) {
                        ob[0]     = acc[mf][nf][0] + b0;
                        ob[P_OUT] = acc[mf][nf][1] + b1;
                    }
                    if (pg + 8 < P_OUT) {
                        ob[8]         = acc[mf][nf][2] + b0;
                        ob[P_OUT + 8] = acc[mf][nf][3] + b1;
                    }
                    #pragma unroll
                    for (int k = 0; k < 4; ++k) acc[mf][nf][k] = 0.0f;
                }
            }
        }
    }
}

extern "C" void kernel_launch(void* const* d_in, const int* in_sizes, int n_in,
                              void* d_out, int out_size)
{
    const float* x  = (const float*)d_in[0];   // (8, 128, 32768)
    const float* W  = (const float*)d_in[1];   // (128, 128, 2)
    const float* bs = (const float*)d_in[2];   // (128,)
    float* out = (float*)d_out;                // (8, 128, 32769)

    cudaFuncSetAttribute(dconv7, cudaFuncAttributeMaxDynamicSharedMemorySize, SM_TOT);

    prep_W<<<64, 256>>>(W);
    dconv7<<<GRIDX, 512, SM_TOT>>>(x, bs, out);
}

// round 8
// speedup vs baseline: 1.4386x; 1.4386x over previous
#include <cuda_runtime.h>
#include <cuda_fp16.h>
#include <cstdint>

#define CIN    128
#define OUTC   128
#define T_IN   32768
#define P_OUT  32769
#define NTILES 2056          // 257 p-tiles * 8 batches
#define GRIDX  152

#define WP 132               // u64 pitch, W pair rows (conflict-free LDS.64)
#define AP 132               // u64 pitch, A rows (conflict-free LDS.64)

// smem byte offsets
#define SM_W    0                        // u64 [64][WP] = 67584
#define SM_A0   67584                    // u64 [32][AP] = 33792
#define SM_A1   101376
#define SM_BIAS 135168
#define SM_TOT  135680

typedef unsigned long long u64;

// W image: [pr][o] u64 = { lo32: f16x2 pair(row r), hi32: f16x2 pair(row r+4) }
// pair(row) = f16x2 { lo: W[o][2*row], hi: W[o][2*row+1] },  r = 8*(pr>>2) + (pr&3)
__device__ __align__(16) u64 g_W64[64 * WP];

__device__ __forceinline__ uint32_t cvt2h(float hi, float lo) {
    uint32_t r;
    asm("cvt.rn.f16x2.f32 %0, %1, %2;" : "=r"(r) : "f"(hi), "f"(lo));
    return r;
}
__device__ __forceinline__ uint32_t lo_residh(uint32_t h, float xhi, float xlo) {
    float fh, fl;
    asm("{ .reg .b16 l, hh; mov.b32 {l, hh}, %2; cvt.f32.f16 %0, hh; cvt.f32.f16 %1, l; }"
        : "=f"(fh), "=f"(fl) : "r"(h));
    return cvt2h(xhi - fh, xlo - fl);
}
__device__ __forceinline__ void mma16816h(float* d, const uint32_t* a, uint32_t b0, uint32_t b1) {
    asm volatile(
        "mma.sync.aligned.m16n8k16.row.col.f32.f16.f16.f32 "
        "{%0,%1,%2,%3}, {%4,%5,%6,%7}, {%8,%9}, {%0,%1,%2,%3};"
        : "+f"(d[0]), "+f"(d[1]), "+f"(d[2]), "+f"(d[3])
        : "r"(a[0]), "r"(a[1]), "r"(a[2]), "r"(a[3]), "r"(b0), "r"(b1));
}

__global__ void prep_W(const float* __restrict__ W) {
    int idx = blockIdx.x * blockDim.x + threadIdx.x;   // 8192
    int pr = idx >> 7, o = idx & 127;
    int r = ((pr >> 2) << 3) | (pr & 3);
    uint32_t pa = cvt2h(W[o * 256 + 2 * r + 1],       W[o * 256 + 2 * r]);
    uint32_t pb = cvt2h(W[o * 256 + 2 * (r + 4) + 1], W[o * 256 + 2 * (r + 4)]);
    g_W64[pr * WP + o] = ((u64)pb << 32) | pa;
}

// LDG: thread (row, q) loads window [p0+8q, p0+8q+10) of channel c*32+row
__device__ __forceinline__ void ldg_chunk(const float* __restrict__ x,
                                          int tile, int c, int row, int q, float* v) {
    int b = tile & 7;
    long p0 = (long)(tile >> 3) * 128;
    const float* gxr = x + (size_t)b * CIN * T_IN + (size_t)(c * 32 + row) * T_IN;
    long pb = p0 + 8 * q;
    if (p0 + 130 <= T_IN) {
        float4 q0 = *reinterpret_cast<const float4*>(gxr + pb);
        float4 q1 = *reinterpret_cast<const float4*>(gxr + pb + 4);
        v[0]=q0.x; v[1]=q0.y; v[2]=q0.z; v[3]=q0.w;
        v[4]=q1.x; v[5]=q1.y; v[6]=q1.z; v[7]=q1.w;
        v[8]=gxr[pb + 8]; v[9]=gxr[pb + 9];
    } else {
        #pragma unroll
        for (int k = 0; k < 10; ++k) {
            long p = pb + k;
            v[k] = (p < T_IN) ? gxr[p] : 0.0f;
        }
    }
}
// cvt + STS: positions [8q, 8q+8), pair(p) = f16x2{x[p], x[p+2]}; u64 = {hi pair, lo pair}
__device__ __forceinline__ void sts_chunk(u64* __restrict__ buf, int row, int q, const float* v) {
    #pragma unroll
    for (int j = 0; j < 4; ++j) {
        uint32_t h0 = cvt2h(v[2*j + 2], v[2*j]);
        uint32_t l0 = lo_residh(h0, v[2*j + 2], v[2*j]);
        uint32_t h1 = cvt2h(v[2*j + 3], v[2*j + 1]);
        uint32_t l1 = lo_residh(h1, v[2*j + 3], v[2*j + 1]);
        uint4 val; val.x = h0; val.y = l0; val.z = h1; val.w = l1;
        *reinterpret_cast<uint4*>(buf + (size_t)row * AP + 8 * q + 2 * j) = val;  // 16B aligned
    }
}

__global__ __launch_bounds__(512, 1)
void dconv8(const float* __restrict__ x,
            const float* __restrict__ bias,
            float* __restrict__ out)
{
    extern __shared__ char smem[];
    u64*   sW    = reinterpret_cast<u64*>(smem + SM_W);
    u64*   sA[2] = { reinterpret_cast<u64*>(smem + SM_A0),
                     reinterpret_cast<u64*>(smem + SM_A1) };
    float* sBias = reinterpret_cast<float*>(smem + SM_BIAS);

    const int tid = threadIdx.x;
    const int lane = tid & 31;
    const int t = lane & 3;
    const int g = lane >> 2;
    const int warp = tid >> 5;
    const int mb = (warp >> 2) * 32;
    const int nb = (warp & 3) * 32;
    const int arow = tid >> 4;      // staging channel-within-chunk 0..31
    const int aq   = tid & 15;      // staging 8-position group 0..15
    const int bx   = blockIdx.x;
    const int nt = (NTILES - 1 - bx) / GRIDX + 1;
    const int nchunks = nt * 4;

    // one-time: W image + bias
    {
        const uint4* src = reinterpret_cast<const uint4*>(g_W64);
        uint4* dst = reinterpret_cast<uint4*>(sW);
        #pragma unroll 4
        for (int i = tid; i < 4224; i += 512) dst[i] = src[i];
    }
    if (tid < 128) sBias[tid] = bias[tid];

    float acc[2][4][4];
    #pragma unroll
    for (int mf = 0; mf < 2; ++mf)
        #pragma unroll
        for (int nf = 0; nf < 4; ++nf)
            #pragma unroll
            for (int i = 0; i < 4; ++i) acc[mf][nf][i] = 0.0f;

    // prologue: stage chunk 0, preload chunk 1 into registers
    float vp[10];
    {
        float v[10];
        ldg_chunk(x, bx, 0, arow, aq, v);
        sts_chunk(sA[0], arow, aq, v);
        #pragma unroll
        for (int k = 0; k < 10; ++k) vp[k] = 0.0f;
        if (nchunks > 1) ldg_chunk(x, bx, 1, arow, aq, vp);
    }
    __syncthreads();

    int i = 0;
    for (int tt = 0; tt < nt; ++tt) {
        #pragma unroll 1
        for (int c = 0; c < 4; ++c, ++i) {
            // STS pending chunk (data LDG'd a full chunk ago — ready now)
            if (i + 1 < nchunks) sts_chunk(sA[(i + 1) & 1], arow, aq, vp);
            // issue LDG for chunk i+2
            float vn[10];
            #pragma unroll
            for (int k = 0; k < 10; ++k) vn[k] = 0.0f;
            if (i + 2 < nchunks) {
                int ii = i + 2;
                ldg_chunk(x, bx + (ii >> 2) * GRIDX, ii & 3, arow, aq, vn);
            }
            // MMA chunk c from buf (i&1): 2 GEMM terms (Ahi*B + Alo*B)
            {
                const u64* Ab = sA[i & 1];
                #pragma unroll
                for (int kl = 0; kl < 4; ++kl) {
                    const u64* wr = sW + (size_t)(16 * c + 4 * kl + t) * WP;
                    u64 w[4];
                    #pragma unroll
                    for (int nf = 0; nf < 4; ++nf) w[nf] = wr[nb + nf * 8 + g];
                    const int lrt = 8 * kl + t;
                    const u64* ar = Ab + (size_t)lrt * AP;
                    #pragma unroll
                    for (int mf = 0; mf < 2; ++mf) {
                        const int pos = mb + mf * 16 + g;
                        u64 a0 = ar[pos],          a1 = ar[pos + 8];
                        u64 a2 = ar[4 * AP + pos], a3 = ar[4 * AP + pos + 8];
                        uint32_t ah[4] = { (uint32_t)a0, (uint32_t)a1, (uint32_t)a2, (uint32_t)a3 };
                        uint32_t al[4] = { (uint32_t)(a0 >> 32), (uint32_t)(a1 >> 32),
                                           (uint32_t)(a2 >> 32), (uint32_t)(a3 >> 32) };
                        #pragma unroll
                        for (int nf = 0; nf < 4; ++nf) {
                            uint32_t b0 = (uint32_t)w[nf], b1 = (uint32_t)(w[nf] >> 32);
                            mma16816h(acc[mf][nf], ah, b0, b1);   // Ahi * B
                            mma16816h(acc[mf][nf], al, b0, b1);   // Alo * B
                        }
                    }
                }
            }
            __syncthreads();
            #pragma unroll
            for (int k = 0; k < 10; ++k) vp[k] = vn[k];
        }

        // epilogue for this tile (next tile's chunk 0 already staged)
        {
            const int tile = bx + tt * GRIDX;
            const int b = tile & 7;
            const long p0 = (long)(tile >> 3) * 128;
            #pragma unroll
            for (int mf = 0; mf < 2; ++mf) {
                long pg = p0 + mb + mf * 16 + g;
                #pragma unroll
                for (int nf = 0; nf < 4; ++nf) {
                    int o = nb + nf * 8 + 2 * t;
                    float b0 = sBias[o], b1 = sBias[o + 1];
                    float* ob = out + ((size_t)b * OUTC + o) * P_OUT + pg;
                    if (pg < P_OUT) {
                        ob[0]     = acc[mf][nf][0] + b0;
                        ob[P_OUT] = acc[mf][nf][1] + b1;
                    }
                    if (pg + 8 < P_OUT) {
                        ob[8]         = acc[mf][nf][2] + b0;
                        ob[P_OUT + 8] = acc[mf][nf][3] + b1;
                    }
                    #pragma unroll
                    for (int k = 0; k < 4; ++k) acc[mf][nf][k] = 0.0f;
                }
            }
        }
    }
}

extern "C" void kernel_launch(void* const* d_in, const int* in_sizes, int n_in,
                              void* d_out, int out_size)
{
    const float* x  = (const float*)d_in[0];   // (8, 128, 32768)
    const float* W  = (const float*)d_in[1];   // (128, 128, 2)
    const float* bs = (const float*)d_in[2];   // (128,)
    float* out = (float*)d_out;                // (8, 128, 32769)

    cudaFuncSetAttribute(dconv8, cudaFuncAttributeMaxDynamicSharedMemorySize, SM_TOT);

    prep_W<<<32, 256>>>(W);
    dconv8<<<GRIDX, 512, SM_TOT>>>(x, bs, out);
}

// round 9
// speedup vs baseline: 1.7290x; 1.2018x over previous
#include <cuda_runtime.h>
#include <cuda_fp16.h>
#include <cstdint>

#define CIN    128
#define OUTC   128
#define T_IN   32768
#define P_OUT  32769
#define NTILES 2056          // 257 p-tiles * 8 batches
#define GRID   304           // 2 CTAs per SM

#define WP 132               // u64 pitch, W pair rows (conflict-free LDS.64)

// smem byte offsets (per CTA: 100864 B -> 2 CTAs/SM)
#define SM_W    0                        // u64 [64][WP] = 67584
#define SM_A0   67584                    // u32 [32][128] = 16384 (XOR-swizzled)
#define SM_A1   83968
#define SM_BIAS 100352
#define SM_TOT  100864

typedef unsigned long long u64;

// W image: [pr][o] u64 = { lo32: f16x2 pair(row r), hi32: f16x2 pair(row r+4) }
// pair(row) = f16x2 { lo: W[o][2*row], hi: W[o][2*row+1] },  r = 8*(pr>>2) + (pr&3)
__device__ __align__(16) u64 g_W64[64 * WP];

__device__ __forceinline__ uint32_t cvt2h(float hi, float lo) {
    uint32_t r;
    asm("cvt.rn.f16x2.f32 %0, %1, %2;" : "=r"(r) : "f"(hi), "f"(lo));
    return r;
}
__device__ __forceinline__ void mma16816h(float* d, const uint32_t* a, uint32_t b0, uint32_t b1) {
    asm volatile(
        "mma.sync.aligned.m16n8k16.row.col.f32.f16.f16.f32 "
        "{%0,%1,%2,%3}, {%4,%5,%6,%7}, {%8,%9}, {%0,%1,%2,%3};"
        : "+f"(d[0]), "+f"(d[1]), "+f"(d[2]), "+f"(d[3])
        : "r"(a[0]), "r"(a[1]), "r"(a[2]), "r"(a[3]), "r"(b0), "r"(b1));
}

__global__ void prep_W(const float* __restrict__ W) {
    int idx = blockIdx.x * blockDim.x + threadIdx.x;   // 8192
    int pr = idx >> 7, o = idx & 127;
    int r = ((pr >> 2) << 3) | (pr & 3);
    uint32_t pa = cvt2h(W[o * 256 + 2 * r + 1],       W[o * 256 + 2 * r]);
    uint32_t pb = cvt2h(W[o * 256 + 2 * (r + 4) + 1], W[o * 256 + 2 * (r + 4)]);
    g_W64[pr * WP + o] = ((u64)pb << 32) | pa;
}

// LDG: thread (row, q) loads window [p0+16q, p0+16q+18) of channel c*32+row
__device__ __forceinline__ void ldgC(const float* __restrict__ x,
                                     int tile, int c, int row, int q, float* v) {
    int b = tile & 7;
    long p0 = (long)(tile >> 3) * 128;
    const float* gxr = x + (size_t)b * CIN * T_IN + (size_t)(c * 32 + row) * T_IN;
    long pb = p0 + 16 * q;
    if (p0 + 130 <= T_IN) {
        float4 q0 = *reinterpret_cast<const float4*>(gxr + pb);
        float4 q1 = *reinterpret_cast<const float4*>(gxr + pb + 4);
        float4 q2 = *reinterpret_cast<const float4*>(gxr + pb + 8);
        float4 q3 = *reinterpret_cast<const float4*>(gxr + pb + 12);
        v[0]=q0.x;  v[1]=q0.y;  v[2]=q0.z;  v[3]=q0.w;
        v[4]=q1.x;  v[5]=q1.y;  v[6]=q1.z;  v[7]=q1.w;
        v[8]=q2.x;  v[9]=q2.y;  v[10]=q2.z; v[11]=q2.w;
        v[12]=q3.x; v[13]=q3.y; v[14]=q3.z; v[15]=q3.w;
        v[16]=gxr[pb + 16]; v[17]=gxr[pb + 17];
    } else {
        #pragma unroll
        for (int k = 0; k < 18; ++k) {
            long p = pb + k;
            v[k] = (p < T_IN) ? gxr[p] : 0.0f;
        }
    }
}
// cvt + STS: entry(pos) = f16x2{x[pos], x[pos+2]} at u32 offset row*128 + (pos ^ 8(row&3)).
// j-rotation ((j + (q>>1)) & 3) makes the uint4 subphases hit all 8 bank groups.
__device__ __forceinline__ void stsC(uint32_t* __restrict__ buf, int row, int q, const float* v) {
    const uint32_t s = (uint32_t)((row & 3) << 3);
    uint32_t* br = buf + row * 128;
    #pragma unroll
    for (int j = 0; j < 4; ++j) {
        int jj = (j + (q >> 1)) & 3;
        const float* p = v + 4 * jj;
        uint4 e;
        e.x = cvt2h(p[2], p[0]);
        e.y = cvt2h(p[3], p[1]);
        e.z = cvt2h(p[4], p[2]);
        e.w = cvt2h(p[5], p[3]);
        *reinterpret_cast<uint4*>(br + (((uint32_t)(16 * q + 4 * jj)) ^ s)) = e;
    }
}

__global__ __launch_bounds__(256, 2)
void dconv9(const float* __restrict__ x,
            const float* __restrict__ bias,
            float* __restrict__ out)
{
    extern __shared__ char smem[];
    u64*      sW    = reinterpret_cast<u64*>(smem + SM_W);
    uint32_t* sA[2] = { reinterpret_cast<uint32_t*>(smem + SM_A0),
                        reinterpret_cast<uint32_t*>(smem + SM_A1) };
    float*    sBias = reinterpret_cast<float*>(smem + SM_BIAS);

    const int tid = threadIdx.x;
    const int lane = tid & 31;
    const int t = lane & 3;
    const int g = lane >> 2;
    const int warp = tid >> 5;
    const int mb = (warp >> 2) * 64;   // 2 M-groups
    const int nb = (warp & 3) * 32;    // 4 N-groups
    const int arow = tid >> 3;         // staging channel 0..31
    const int aq   = tid & 7;          // staging 16-pos group 0..7
    const int bx = blockIdx.x;
    const int nt = (NTILES - 1 - bx) / GRID + 1;
    const int nchunks = nt * 4;

    // one-time: W image + bias
    {
        const uint4* src = reinterpret_cast<const uint4*>(g_W64);
        uint4* dst = reinterpret_cast<uint4*>(sW);
        #pragma unroll 4
        for (int i = tid; i < 4224; i += 256) dst[i] = src[i];
    }
    if (tid < 128) sBias[tid] = bias[tid];

    float acc[4][4][4];
    #pragma unroll
    for (int mf = 0; mf < 4; ++mf)
        #pragma unroll
        for (int nf = 0; nf < 4; ++nf)
            #pragma unroll
            for (int i = 0; i < 4; ++i) acc[mf][nf][i] = 0.0f;

    float v[18];
    ldgC(x, bx, 0, arow, aq, v);

    int i = 0;
    for (int tt = 0; tt < nt; ++tt) {
        #pragma unroll 1
        for (int c = 0; c < 4; ++c, ++i) {
            // stage chunk i (v loaded last iteration; LDG latency covered by prior MMA)
            stsC(sA[i & 1], arow, aq, v);
            if (i + 1 < nchunks) {
                int ii = i + 1;
                ldgC(x, bx + (ii >> 2) * GRID, ii & 3, arow, aq, v);
            }
            __syncthreads();

            // MMA chunk c from A[i&1]: single fp16 term
            const uint32_t* Ab = sA[i & 1];
            #pragma unroll
            for (int kl = 0; kl < 4; ++kl) {
                const u64* wr = sW + (size_t)(16 * c + 4 * kl + t) * WP;
                u64 w[4];
                #pragma unroll
                for (int nf = 0; nf < 4; ++nf) w[nf] = wr[nb + nf * 8 + g];
                const uint32_t sx = (uint32_t)(t << 3);
                const uint32_t* A0 = Ab + (8 * kl + t) * 128;
                const uint32_t* A1 = A0 + 4 * 128;
                #pragma unroll
                for (int mf = 0; mf < 4; ++mf) {
                    const uint32_t pos = (uint32_t)(mb + mf * 16 + g);
                    uint32_t a[4];
                    a[0] = A0[pos ^ sx];
                    a[1] = A0[(pos + 8) ^ sx];
                    a[2] = A1[pos ^ sx];
                    a[3] = A1[(pos + 8) ^ sx];
                    #pragma unroll
                    for (int nf = 0; nf < 4; ++nf)
                        mma16816h(acc[mf][nf], a, (uint32_t)w[nf], (uint32_t)(w[nf] >> 32));
                }
            }
        }

        // epilogue for this tile
        {
            const int tile = bx + tt * GRID;
            const int b = tile & 7;
            const long p0 = (long)(tile >> 3) * 128;
            #pragma unroll
            for (int mf = 0; mf < 4; ++mf) {
                long pg = p0 + mb + mf * 16 + g;
                #pragma unroll
                for (int nf = 0; nf < 4; ++nf) {
                    int o = nb + nf * 8 + 2 * t;
                    float b0 = sBias[o], b1 = sBias[o + 1];
                    float* ob = out + ((size_t)b * OUTC + o) * P_OUT + pg;
                    if (pg < P_OUT) {
                        ob[0]     = acc[mf][nf][0] + b0;
                        ob[P_OUT] = acc[mf][nf][1] + b1;
                    }
                    if (pg + 8 < P_OUT) {
                        ob[8]         = acc[mf][nf][2] + b0;
                        ob[P_OUT + 8] = acc[mf][nf][3] + b1;
                    }
                    #pragma unroll
                    for (int k = 0; k < 4; ++k) acc[mf][nf][k] = 0.0f;
                }
            }
        }
    }
}

extern "C" void kernel_launch(void* const* d_in, const int* in_sizes, int n_in,
                              void* d_out, int out_size)
{
    const float* x  = (const float*)d_in[0];   // (8, 128, 32768)
    const float* W  = (const float*)d_in[1];   // (128, 128, 2)
    const float* bs = (const float*)d_in[2];   // (128,)
    float* out = (float*)d_out;                // (8, 128, 32769)

    cudaFuncSetAttribute(dconv9, cudaFuncAttributeMaxDynamicSharedMemorySize, SM_TOT);

    prep_W<<<32, 256>>>(W);
    dconv9<<<GRID, 256, SM_TOT>>>(x, bs, out);
}